// round 7
// baseline (speedup 1.0000x reference)
#include <cuda_runtime.h>
#include <cuda_bf16.h>
#include <cstdint>

#define NPOS 9
#define NROWS 16384          // T*B
#define D 128
#define TILE_M 128
#define GRID_CTAS 148        // 1 CTA/SM, wave-1 co-resident -> device barrier safe
#define ROWS_PER_CTA 111     // 148*111 = 16428 >= 16384
#define NBFRAG (NPOS * 128 * 32)   // 36864 uint4 entries (9 matrices, fragment-packed)

__device__ int g_count[NPOS];        // zero at entry; last CTA resets
__device__ int g_list[NPOS * NROWS];
__device__ uint4 g_bfrag[NBFRAG];    // {BH0,BH1,BL0,BL1} per (p,qn,lane)
__device__ int g_arrive;
__device__ int g_exit;

// smem: A fragments only
#define OFF_AHI 0
#define OFF_ALO 32768
#define OFF_AUX 65536
#define SMEM_BYTES (65536 + 128)

// bf16 hi/lo split of a float pair, packed into b32 (low element in low half)
__device__ __forceinline__ void split2(float x, float y, uint32_t& hi, uint32_t& lo) {
    __nv_bfloat162 h = __floats2bfloat162_rn(x, y);
    float hx = __bfloat162float(h.x), hy = __bfloat162float(h.y);
    __nv_bfloat162 l = __floats2bfloat162_rn(x - hx, y - hy);
    hi = *(uint32_t*)&h;
    lo = *(uint32_t*)&l;
}

#define MMA16816(c0, c1, c2, c3, a0, a1, a2, a3, b0, b1)                      \
    asm volatile(                                                             \
        "mma.sync.aligned.m16n8k16.row.col.f32.bf16.bf16.f32 "                \
        "{%0,%1,%2,%3}, {%4,%5,%6,%7}, {%8,%9}, {%0,%1,%2,%3};"               \
        : "+f"(c0), "+f"(c1), "+f"(c2), "+f"(c3)                              \
        : "r"(a0), "r"(a1), "r"(a2), "r"(a3), "r"(b0), "r"(b1))

__global__ void __launch_bounds__(256, 1)
fused_transfer(const void* __restrict__ pos_raw,
               const float* __restrict__ x,
               const float* __restrict__ table,
               float* __restrict__ out)
{
    extern __shared__ char base[];
    int* aux = (int*)(base + OFF_AUX);

    const int tid  = threadIdx.x;
    const int cid  = blockIdx.x;
    const int wid  = tid >> 5;
    const int lane = tid & 31;
    const int g    = lane >> 2;       // fragment groupID
    const int tig  = lane & 3;        // thread-in-group

    // ============ PRE-BARRIER: histogram slice + B fragment conversion ======
    {
        if (tid < NPOS) aux[tid] = 0;
        // dtype probe: abs word idx cid*64+tid <= 147*64+255 = 9663, in-bounds
        // under BOTH int32 (16384 words) and int64 (32768 words) views.
        // int64 => odd absolute words are zero high-words (values 0..15).
        const int* pos32 = (const int*)pos_raw;
        int pw = pos32[cid * 64 + tid];
        int is32 = __syncthreads_or(((cid * 64 + tid) & 1) && (pw != 0));

        int row  = cid * ROWS_PER_CTA + tid;
        int have = (tid < ROWS_PER_CTA) && (row < NROWS);
        int r = 0, local = 0;
        if (have) {
            int p = is32 ? pos32[row] : (int)((const long long*)pos_raw)[row];
            r = (p < 8) ? p : 8;
            local = atomicAdd(&aux[r], 1);
        }
        __syncthreads();
        if (tid < NPOS) aux[9 + tid] = atomicAdd(&g_count[tid], aux[tid]);
        __syncthreads();
        if (have) g_list[r * NROWS + aux[9 + r] + local] = row;

        // B fragment conversion: one uint4 entry per thread chip-wide.
        // entry id -> (p, qn, ln); fragment regs for MMA n-block nb, k-chunk q.
        int id = cid * 256 + tid;
        if (id < NBFRAG) {
            int p   = id >> 12;            // / 4096
            int rem = id & 4095;
            int qn  = rem >> 5;            // 0..127  (q*16+nb)
            int ln  = rem & 31;
            int q   = qn >> 4, nb = qn & 15;
            int gg  = ln >> 2, tg = ln & 3;
            int e   = nb * 8 + gg;
            int k0  = 16 * q + 2 * tg;
            const float* Mp = table + p * D * D;
            float v0 = Mp[(k0    ) * D + e];
            float v1 = Mp[(k0 + 1) * D + e];
            float v2 = Mp[(k0 + 8) * D + e];
            float v3 = Mp[(k0 + 9) * D + e];
            uint32_t h0, l0, h1, l1;
            split2(v0, v1, h0, l0);
            split2(v2, v3, h1, l1);
            g_bfrag[id] = make_uint4(h0, h1, l0, l1);
        }
    }

    // ============ device-wide barrier (148 CTAs, one wave) ===================
    __syncthreads();
    if (tid == 0) {
        __threadfence();
        atomicAdd(&g_arrive, 1);
        while (*(volatile int*)&g_arrive < GRID_CTAS) { __nanosleep(64); }
        __threadfence();
    }
    __syncthreads();

    // ============ plan: flat item id == cid (items <= 137 <= 148) ============
    int myp = -1, chunk = 0, cnt = 0, total = 0;
    #pragma unroll
    for (int i = 0; i < NPOS; i++) {
        int c = __ldcg(&g_count[i]);
        int it = (c + TILE_M - 1) / TILE_M;
        if (cid >= total && cid < total + it) { myp = i; chunk = cid - total; cnt = c; }
        total += it;
    }

    if (myp >= 0) {
        int row0  = chunk * TILE_M;
        int nrows = cnt - row0;
        if (nrows > TILE_M) nrows = TILE_M;
        const int* list = g_list + myp * NROWS + row0;

        // ---- A gather: x rows -> fragment-packed bf16 hi/lo in smem ----
        // slot(w,q,lane,reg) at byte (w*8+q)*512 + lane*16 + reg*4
        {
            int rA = tid >> 1;                  // tile-local row
            int kh = tid & 1;                   // k half: q in [4kh, 4kh+4)
            int grow = (rA < nrows) ? __ldcg(&list[rA]) : -1;
            int aw = rA >> 4, rr = rA & 15, gg = rr & 7, up = rr >> 3;
            #pragma unroll
            for (int qq = 0; qq < 4; qq++) {
                int q = kh * 4 + qq;
                float4 f0, f1, f2, f3;
                if (grow >= 0) {
                    const float4* src = (const float4*)(x + grow * D + q * 16);
                    f0 = src[0]; f1 = src[1]; f2 = src[2]; f3 = src[3];
                } else {
                    f0 = f1 = f2 = f3 = make_float4(0.f, 0.f, 0.f, 0.f);
                }
                float kv[16] = {f0.x, f0.y, f0.z, f0.w, f1.x, f1.y, f1.z, f1.w,
                                f2.x, f2.y, f2.z, f2.w, f3.x, f3.y, f3.z, f3.w};
                #pragma unroll
                for (int t = 0; t < 4; t++) {
                    uint32_t hL, lL, hH, lH;
                    split2(kv[2 * t], kv[2 * t + 1], hL, lL);
                    split2(kv[2 * t + 8], kv[2 * t + 9], hH, lH);
                    uint32_t off = (aw * 8 + q) * 512 + (gg * 4 + t) * 16 + up * 4;
                    *(uint32_t*)(base + OFF_AHI + off)     = hL;   // reg up
                    *(uint32_t*)(base + OFF_AHI + off + 8) = hH;   // reg up+2
                    *(uint32_t*)(base + OFF_ALO + off)     = lL;
                    *(uint32_t*)(base + OFF_ALO + off + 8) = lH;
                }
            }
        }
        __syncthreads();

        // ---- mainloop: A from smem, B fragments streamed from L2 ----
        float acc[16][4];
        #pragma unroll
        for (int nb = 0; nb < 16; nb++)
            #pragma unroll
            for (int r = 0; r < 4; r++) acc[nb][r] = 0.f;

        const uint4* bfr = g_bfrag + myp * 4096;

        #pragma unroll
        for (int q = 0; q < 8; q++) {
            uint32_t abase = (wid * 8 + q) * 512 + lane * 16;
            uint4 AH = *(const uint4*)(base + OFF_AHI + abase);
            uint4 AL = *(const uint4*)(base + OFF_ALO + abase);
            #pragma unroll
            for (int nb = 0; nb < 16; nb++) {
                uint4 bv = __ldg(&bfr[(q * 16 + nb) * 32 + lane]); // {BH0,BH1,BL0,BL1}
                MMA16816(acc[nb][0], acc[nb][1], acc[nb][2], acc[nb][3],
                         AH.x, AH.y, AH.z, AH.w, bv.x, bv.y);
                MMA16816(acc[nb][0], acc[nb][1], acc[nb][2], acc[nb][3],
                         AH.x, AH.y, AH.z, AH.w, bv.z, bv.w);
                MMA16816(acc[nb][0], acc[nb][1], acc[nb][2], acc[nb][3],
                         AL.x, AL.y, AL.z, AL.w, bv.x, bv.y);
            }
        }

        // ---- epilogue: c0,c1 -> row g; c2,c3 -> row g+8; cols nb*8+2tig ----
        {
            int r0 = wid * 16 + g;
            int r1 = r0 + 8;
            int grow0 = (r0 < nrows) ? __ldcg(&list[r0]) : -1;
            int grow1 = (r1 < nrows) ? __ldcg(&list[r1]) : -1;
            #pragma unroll
            for (int nb = 0; nb < 16; nb++) {
                int col = nb * 8 + 2 * tig;
                if (grow0 >= 0)
                    *(float2*)(out + grow0 * D + col) = make_float2(acc[nb][0], acc[nb][1]);
                if (grow1 >= 0)
                    *(float2*)(out + grow1 * D + col) = make_float2(acc[nb][2], acc[nb][3]);
            }
        }
    }

    // ============ exit: last CTA resets globals for next replay ==============
    __syncthreads();
    if (tid == 0) {
        int e = atomicAdd(&g_exit, 1);
        if (e == GRID_CTAS - 1) {
            #pragma unroll
            for (int i = 0; i < NPOS; i++) g_count[i] = 0;
            g_arrive = 0;
            g_exit = 0;
            __threadfence();
        }
    }
}

// ---------------------------------------------------------------------------
extern "C" void kernel_launch(void* const* d_in, const int* in_sizes, int n_in,
                              void* d_out, int out_size) {
    const void*  positions = d_in[0];                 // int32/int64 [T,B] auto-detected
    const float* outputs   = (const float*)d_in[1];   // f32 [T,B,128]
    const float* table     = (const float*)d_in[2];   // f32 [9,128,128]
    float*       out       = (float*)d_out;           // f32 [T,B,128]
    (void)in_sizes; (void)n_in; (void)out_size;

    static cudaError_t attr_once = cudaFuncSetAttribute(
        fused_transfer, cudaFuncAttributeMaxDynamicSharedMemorySize, SMEM_BYTES);
    (void)attr_once;

    fused_transfer<<<GRID_CTAS, 256, SMEM_BYTES>>>(positions, outputs, table, out);
}